// round 8
// baseline (speedup 1.0000x reference)
#include <cuda_runtime.h>
#include <cstdint>

// MeanAggregator: multi-pass L2 temporal blocking + cp.async smem-staged gathers.
// out[b,:] = mean_k table[neighs[b,k],:], B=50000, K=32, table 500000x128 f32.
//
// 4 launches; pass p gathers rows in [p*125K,(p+1)*125K) (64MB segment + 26MB
// out RMW + 13MB idx fits 126MB L2 -> repeat row touches hit L2). Per warp per
// burst: up to 12 rows fetched via one LDGSTS.128 per row (lane l copies bytes
// [16l,16l+16)) into a per-warp smem buffer -> MLP=12 with no staging regs.
// Accumulate: lane l owns cols [4l,4l+4): one LDS.128 + 4 FADD per row.

#define BATCH   50000
#define DEGREE  32
#define D_FEAT  128
#define WARPS_PER_BLOCK 8
#define THREADS 256
#define NSEG    4
#define SEG     (500000 / NSEG)
#define ROWS_BUF 12
#define FULL    0xffffffffu

__device__ int g_idx_is64;

// int64 indices in [0,500000) have all odd 32-bit words == 0; int32 data has
// random values there (P(128 zeros) ~ 0).
__global__ void detect_idx_dtype(const unsigned int* __restrict__ n32)
{
    bool all_zero = true;
    #pragma unroll
    for (int i = 1; i < 256; i += 2) {
        if (n32[i] != 0u) { all_zero = false; break; }
    }
    g_idx_is64 = all_zero ? 1 : 0;
}

__device__ __forceinline__ void cp_async16(uint32_t smem_addr, const float* gptr)
{
    asm volatile("cp.async.cg.shared.global [%0], [%1], 16;"
                 :: "r"(smem_addr), "l"(gptr));
}

__device__ __forceinline__ void cp_async_wait_all()
{
    asm volatile("cp.async.wait_all;" ::: "memory");
}

__global__ __launch_bounds__(THREADS)
void mean_agg_pass(const void* __restrict__ neighs_raw,
                   const float* __restrict__ table,  // [500000, 128] f32
                   float4* __restrict__ out,         // [50000, 32] float4 (raw sums until last pass)
                   int pass)
{
    // Per-warp staging: ROWS_BUF rows x 512B. 8 * 12 * 512 = 48KB static smem.
    __shared__ float4 buf[WARPS_PER_BLOCK][ROWS_BUF][32];

    const int gwarp = (blockIdx.x * THREADS + threadIdx.x) >> 5;  // node id
    const int w     = threadIdx.x >> 5;
    const int lane  = threadIdx.x & 31;
    if (gwarp >= BATCH) return;   // BATCH % WARPS_PER_BLOCK == 0: whole warps only

    // Coalesced load of this node's 32 indices (lane k -> index k).
    long long my_idx;
    if (g_idx_is64) {
        my_idx = __ldg(&((const long long*)neighs_raw)[(size_t)gwarp * DEGREE + lane]);
    } else {
        my_idx = (long long)__ldg(&((const int*)neighs_raw)[(size_t)gwarp * DEGREE + lane]);
    }

    const long long lo = (long long)pass * SEG;
    const long long hi = lo + SEG;
    unsigned m = __ballot_sync(FULL, my_idx >= lo && my_idx < hi);

    float4 acc = make_float4(0.f, 0.f, 0.f, 0.f);

    const uint32_t sbase =
        (uint32_t)__cvta_generic_to_shared(&buf[w][0][lane]);

    while (m) {
        int cnt = 0;
        // Issue up to ROWS_BUF independent row copies (uniform loop: m is
        // warp-uniform, shfl source j is uniform).
        while (m && cnt < ROWS_BUF) {
            const int j = __ffs(m) - 1;
            m &= (m - 1);
            const long long idx = __shfl_sync(FULL, my_idx, j);
            cp_async16(sbase + (uint32_t)cnt * 512u,
                       table + (size_t)idx * D_FEAT + lane * 4);
            ++cnt;
        }
        cp_async_wait_all();
        __syncwarp();
        for (int i = 0; i < cnt; ++i) {
            const float4 v = buf[w][i][lane];
            acc.x += v.x; acc.y += v.y; acc.z += v.z; acc.w += v.w;
        }
        __syncwarp();  // protect buffer reuse if a second burst follows
    }

    float4* o = &out[(size_t)gwarp * (D_FEAT / 4) + lane];
    if (pass != 0) {
        const float4 p = *o;   // partial sums: L2-resident (26MB), normal caching
        acc.x += p.x; acc.y += p.y; acc.z += p.z; acc.w += p.w;
    }
    if (pass == NSEG - 1) {
        const float s = 1.0f / (float)DEGREE;
        acc.x *= s; acc.y *= s; acc.z *= s; acc.w *= s;
    }
    *o = acc;
}

extern "C" void kernel_launch(void* const* d_in, const int* in_sizes, int n_in,
                              void* d_out, int out_size)
{
    const void*  neighs = d_in[0];
    const float* table  = (const float*)d_in[1];
    float4*      out    = (float4*)d_out;

    detect_idx_dtype<<<1, 1>>>((const unsigned int*)neighs);

    const int blocks = (BATCH + WARPS_PER_BLOCK - 1) / WARPS_PER_BLOCK;
    for (int p = 0; p < NSEG; ++p)
        mean_agg_pass<<<blocks, THREADS>>>(neighs, table, out, p);
}